// round 1
// baseline (speedup 1.0000x reference)
#include <cuda_runtime.h>
#include <cuda_bf16.h>
#include <math.h>

// Problem constants
#define BB   4
#define NN   16384
#define MM   (BB * NN)        // 65536 points total
#define HID  128
#define RESO 128
#define R2   (RESO * RESO)    // 16384 bins per batch
#define NBLK 5
#define LDXH 384              // row buffer: [H(128) | net(128) | pooled(128)]

// ---------------------------------------------------------------------------
// Scratch (static __device__ arrays; no runtime allocation)
// ---------------------------------------------------------------------------
__device__ int      g_idx[MM];
__device__ float    g_XH[(size_t)MM * LDXH];              // ~100 MB
__device__ unsigned g_bins[(size_t)BB * R2 * HID];        // max-pool bins / sum buffer (aliased)
__device__ float    g_cnt[BB * R2];
__device__ float    g_wcat[NBLK * HID * 384];             // [W1 | Ws] per block

// ---------------------------------------------------------------------------
// Monotone float<->uint encoding for atomicMax on floats
// ---------------------------------------------------------------------------
__device__ __forceinline__ unsigned f_enc(float x) {
    unsigned u = __float_as_uint(x);
    return (u & 0x80000000u) ? ~u : (u | 0x80000000u);
}
__device__ __forceinline__ float f_dec(unsigned u) {
    return (u & 0x80000000u) ? __uint_as_float(u & 0x7FFFFFFFu)
                             : __uint_as_float(~u);
}

// ---------------------------------------------------------------------------
// Build Wcat[k] = [blk_fc1_w[k] (128x128) | blk_sc_w[k] (128x256)]  (128x384)
// ---------------------------------------------------------------------------
__global__ void k_wcat(const float* __restrict__ w1, const float* __restrict__ ws) {
    int t = blockIdx.x * blockDim.x + threadIdx.x;
    const int total = NBLK * HID * 384;
    if (t >= total) return;
    int k = t / (HID * 384);
    int r = t % (HID * 384);
    int n = r / 384;
    int c = r % 384;
    float v;
    if (c < 128) v = w1[((size_t)k * HID + n) * 128 + c];
    else         v = ws[((size_t)k * HID + n) * 256 + (c - 128)];
    g_wcat[t] = v;
}

// ---------------------------------------------------------------------------
// fc_pos + bin index. One block per point, 256 threads = 256 outputs.
// Writes to XH cols [128:384].
// ---------------------------------------------------------------------------
__global__ void k_pos(const float* __restrict__ pts,
                      const float* __restrict__ w,
                      const float* __restrict__ b) {
    int m = blockIdx.x;
    int j = threadIdx.x;
    float p0 = pts[(size_t)m * 3 + 0];
    float p1 = pts[(size_t)m * 3 + 1];
    float p2 = pts[(size_t)m * 3 + 2];
    float v = b[j] + p0 * w[j * 3 + 0] + p1 * w[j * 3 + 1] + p2 * w[j * 3 + 2];
    g_XH[(size_t)m * LDXH + 128 + j] = v;
    if (j == 0) {
        int gx = (int)(p0 * (float)RESO);
        int gy = (int)(p1 * (float)RESO);
        gx = min(max(gx, 0), RESO - 1);
        gy = min(max(gy, 0), RESO - 1);
        g_idx[m] = gx + RESO * gy;
    }
}

// ---------------------------------------------------------------------------
// Generic GEMM: C[M x 128] = act(A[M x K]) @ W^T + bias
//   A = g_XH rows, starting at column a_col0 (K contiguous cols)
//   act = relu on k-indices < relu_limit, identity otherwise
//   W: (128 x K) row-major; if wsel >= 0, W = g_wcat + wsel*128*384
//   C written into g_XH at column c_col0
// Tiling: BM=128, BN=128(full), BK=16; 256 threads; 8x8 per-thread tile.
// K and M are multiples of 16/128 for this problem -> no bounds checks.
// ---------------------------------------------------------------------------
__global__ void __launch_bounds__(256, 2) k_gemm(
    int a_col0, const float* __restrict__ Wg, int wsel,
    int K, int relu_limit, const float* __restrict__ bias, int c_col0)
{
    const float* W = (wsel >= 0) ? (g_wcat + (size_t)wsel * HID * 384) : Wg;

    __shared__ float As[16][132];   // [k][m], padded (132*4B = 16B-aligned rows)
    __shared__ float Bs[16][132];   // [k][n]

    int tid = threadIdx.x;
    int m0  = blockIdx.x * 128;
    int ty  = tid >> 4;             // 0..15 -> rows ty*8..ty*8+7
    int tx  = tid & 15;             // 0..15 -> cols tx*8..tx*8+7

    float acc[8][8];
    #pragma unroll
    for (int i = 0; i < 8; i++)
        #pragma unroll
        for (int j = 0; j < 8; j++) acc[i][j] = 0.f;

    const float* Abase = g_XH + (size_t)m0 * LDXH + a_col0;

    for (int k0 = 0; k0 < K; k0 += 16) {
        #pragma unroll
        for (int i = 0; i < 2; i++) {
            int f   = tid + i * 256;     // 0..511
            int row = f >> 2;            // 0..127
            int c4  = (f & 3) << 2;      // 0,4,8,12
            // A tile (with relu; relu_limit is a multiple of 4, whole-vec test ok)
            float4 v = *(const float4*)(Abase + (size_t)row * LDXH + k0 + c4);
            if (k0 + c4 < relu_limit) {
                v.x = fmaxf(v.x, 0.f); v.y = fmaxf(v.y, 0.f);
                v.z = fmaxf(v.z, 0.f); v.w = fmaxf(v.w, 0.f);
            }
            As[c4 + 0][row] = v.x; As[c4 + 1][row] = v.y;
            As[c4 + 2][row] = v.z; As[c4 + 3][row] = v.w;
            // W tile
            float4 w4 = *(const float4*)(W + (size_t)row * K + k0 + c4);
            Bs[c4 + 0][row] = w4.x; Bs[c4 + 1][row] = w4.y;
            Bs[c4 + 2][row] = w4.z; Bs[c4 + 3][row] = w4.w;
        }
        __syncthreads();

        #pragma unroll
        for (int kk = 0; kk < 16; kk++) {
            float a[8], b[8];
            *(float4*)&a[0] = *(const float4*)&As[kk][ty * 8];
            *(float4*)&a[4] = *(const float4*)&As[kk][ty * 8 + 4];
            *(float4*)&b[0] = *(const float4*)&Bs[kk][tx * 8];
            *(float4*)&b[4] = *(const float4*)&Bs[kk][tx * 8 + 4];
            #pragma unroll
            for (int i = 0; i < 8; i++)
                #pragma unroll
                for (int j = 0; j < 8; j++)
                    acc[i][j] = fmaf(a[i], b[j], acc[i][j]);
        }
        __syncthreads();
    }

    float* Cbase = g_XH + (size_t)m0 * LDXH + c_col0;
    float bv[8];
    #pragma unroll
    for (int j = 0; j < 8; j++) bv[j] = bias[tx * 8 + j];
    #pragma unroll
    for (int i = 0; i < 8; i++) {
        int m = ty * 8 + i;
        #pragma unroll
        for (int j = 0; j < 8; j += 4) {
            float4 v;
            v.x = acc[i][j + 0] + bv[j + 0];
            v.y = acc[i][j + 1] + bv[j + 1];
            v.z = acc[i][j + 2] + bv[j + 2];
            v.w = acc[i][j + 3] + bv[j + 3];
            *(float4*)(Cbase + (size_t)m * LDXH + tx * 8 + j) = v;
        }
    }
}

// ---------------------------------------------------------------------------
// Zero bins (encoded -inf floor for max / 0.0f for sums) and counts
// ---------------------------------------------------------------------------
__global__ void k_zero() {
    size_t t = (size_t)blockIdx.x * blockDim.x + threadIdx.x;
    const size_t nb = (size_t)BB * R2 * HID;
    if (t < nb) g_bins[t] = 0u;
    if (t < (size_t)BB * R2) g_cnt[t] = 0.f;
}

// net lives in XH cols [128:256]; scatter-max into bins
__global__ void k_smax() {
    int t = blockIdx.x * blockDim.x + threadIdx.x;   // < MM*128
    int m = t >> 7, f = t & 127;
    int b = m >> 14;                                  // N = 16384
    float v = g_XH[(size_t)m * LDXH + 128 + f];
    unsigned* dst = &g_bins[((size_t)(b << 14) + g_idx[m]) * HID + f];
    atomicMax(dst, f_enc(v));
}

// gather pooled into XH cols [256:384]
__global__ void k_gather() {
    int t = blockIdx.x * blockDim.x + threadIdx.x;
    int m = t >> 7, f = t & 127;
    int b = m >> 14;
    unsigned u = g_bins[((size_t)(b << 14) + g_idx[m]) * HID + f];
    g_XH[(size_t)m * LDXH + 256 + f] = f_dec(u);
}

// fc_c output lives in XH cols [0:128]; scatter-add sums + counts
__global__ void k_ssum() {
    int t = blockIdx.x * blockDim.x + threadIdx.x;
    int m = t >> 7, f = t & 127;
    int b = m >> 14;
    float v = g_XH[(size_t)m * LDXH + f];
    float* sums = (float*)g_bins;
    atomicAdd(&sums[((size_t)(b << 14) + g_idx[m]) * HID + f], v);
    if (f == 0) atomicAdd(&g_cnt[(b << 14) + g_idx[m]], 1.0f);
}

// mean + transpose: out[b][c][bin] = sums[b][bin][c] / max(cnt,1)
__global__ void k_final(float* __restrict__ out) {
    __shared__ float s[32][33];
    __shared__ float sc[32];
    int b    = blockIdx.z;
    int bin0 = blockIdx.x * 32;
    int c0   = blockIdx.y * 32;
    const float* sums = (const float*)g_bins;

    #pragma unroll
    for (int i = 0; i < 4; i++) {
        int binl = threadIdx.y + i * 8;
        s[binl][threadIdx.x] =
            sums[((size_t)(b * R2 + bin0 + binl)) * HID + c0 + threadIdx.x];
    }
    if (threadIdx.y == 0)
        sc[threadIdx.x] = fmaxf(g_cnt[b * R2 + bin0 + threadIdx.x], 1.0f);
    __syncthreads();

    #pragma unroll
    for (int i = 0; i < 4; i++) {
        int c = c0 + threadIdx.y + i * 8;
        out[((size_t)(b * HID + c)) * R2 + bin0 + threadIdx.x] =
            s[threadIdx.x][threadIdx.y + i * 8] / sc[threadIdx.x];
    }
}

// ---------------------------------------------------------------------------
// Launch
// ---------------------------------------------------------------------------
extern "C" void kernel_launch(void* const* d_in, const int* in_sizes, int n_in,
                              void* d_out, int out_size) {
    const float* points    = (const float*)d_in[0];
    const float* fc_pos_w  = (const float*)d_in[1];
    const float* fc_pos_b  = (const float*)d_in[2];
    const float* blk_fc0_w = (const float*)d_in[3];
    const float* blk_fc0_b = (const float*)d_in[4];
    const float* blk_fc1_w = (const float*)d_in[5];
    const float* blk_fc1_b = (const float*)d_in[6];
    const float* blk_sc_w  = (const float*)d_in[7];
    const float* fc_c_w    = (const float*)d_in[8];
    const float* fc_c_b    = (const float*)d_in[9];
    float* out = (float*)d_out;

    const int GEMM_BLOCKS = MM / 128;          // 512
    const int PF_THREADS  = MM * HID;          // 8.4M point*feat threads
    const int PF_BLOCKS   = PF_THREADS / 256;  // 32768

    // Weight concat [W1 | Ws] per block
    k_wcat<<<(NBLK * HID * 384 + 255) / 256, 256>>>(blk_fc1_w, blk_sc_w);

    // fc_pos -> XH[:,128:384], bin indices
    k_pos<<<MM, 256>>>(points, fc_pos_w, fc_pos_b);

    // Block 0: H = relu(X)@W0^T + b0 ; net = relu(H)@W1^T + X@Ws^T + b1
    k_gemm<<<GEMM_BLOCKS, 256>>>(128, blk_fc0_w, -1, 256, 256, blk_fc0_b, 0);
    k_gemm<<<GEMM_BLOCKS, 256>>>(0, nullptr, 0, 384, 128, blk_fc1_b, 128);

    // Blocks 1..4: pool(max) -> concat -> resblock
    for (int k = 1; k < NBLK; k++) {
        k_zero<<<32768, 256>>>();
        k_smax<<<PF_BLOCKS, 256>>>();
        k_gather<<<PF_BLOCKS, 256>>>();
        k_gemm<<<GEMM_BLOCKS, 256>>>(128, blk_fc0_w + (size_t)k * HID * 256, -1,
                                     256, 256, blk_fc0_b + k * HID, 0);
        k_gemm<<<GEMM_BLOCKS, 256>>>(0, nullptr, k, 384, 128,
                                     blk_fc1_b + k * HID, 128);
    }

    // fc_c: relu(net) @ fc_c_w^T + b -> XH[:,0:128]
    k_gemm<<<GEMM_BLOCKS, 256>>>(128, fc_c_w, -1, 128, 128, fc_c_b, 0);

    // scatter_mean + transposed plane write
    k_zero<<<32768, 256>>>();
    k_ssum<<<PF_BLOCKS, 256>>>();
    dim3 fgrid(R2 / 32, HID / 32, BB);
    dim3 fblk(32, 8);
    k_final<<<fgrid, fblk>>>(out);
}

// round 5
// speedup vs baseline: 1.8071x; 1.8071x over previous
#include <cuda_runtime.h>
#include <cuda_bf16.h>
#include <math.h>
#include <cstdint>

// Problem constants
#define BB   4
#define NN   16384
#define MM   (BB * NN)        // 65536 points total
#define HID  128
#define RESO 128
#define R2   (RESO * RESO)
#define NBLK 5
#define LDXH 384              // row buffer: [H(128) | net(128) | pooled(128)]

// Weight plane offsets (element index into g_wh/g_wl)
#define WOFF_FC0(k)  ((size_t)(k) * 32768)
#define WOFF_WCAT(k) (163840 + (size_t)(k) * 49152)
#define WOFF_FCC     409600
#define WTOTAL       425984

// ---------------------------------------------------------------------------
// Scratch
// ---------------------------------------------------------------------------
__device__ int           g_idx[MM];
__device__ float         g_XH[(size_t)MM * LDXH];          // ~100 MB
__device__ unsigned      g_bins[(size_t)BB * R2 * HID];
__device__ float         g_cnt[BB * R2];
__device__ __nv_bfloat16 g_wh[WTOTAL];
__device__ __nv_bfloat16 g_wl[WTOTAL];

// ---------------------------------------------------------------------------
// Helpers
// ---------------------------------------------------------------------------
__device__ __forceinline__ unsigned f_enc(float x) {
    unsigned u = __float_as_uint(x);
    return (u & 0x80000000u) ? ~u : (u | 0x80000000u);
}
__device__ __forceinline__ float f_dec(unsigned u) {
    return (u & 0x80000000u) ? __uint_as_float(u & 0x7FFFFFFFu) : __uint_as_float(~u);
}

__device__ __forceinline__ void split2(float a, float b, uint32_t& hp, uint32_t& lp) {
    __nv_bfloat16 ha = __float2bfloat16(a), hb = __float2bfloat16(b);
    float ra = a - __bfloat162float(ha);
    float rb = b - __bfloat162float(hb);
    __nv_bfloat16 la = __float2bfloat16(ra), lb = __float2bfloat16(rb);
    hp = (uint32_t)__bfloat16_as_ushort(ha) | ((uint32_t)__bfloat16_as_ushort(hb) << 16);
    lp = (uint32_t)__bfloat16_as_ushort(la) | ((uint32_t)__bfloat16_as_ushort(lb) << 16);
}

// mma.sync m16n8k16 bf16 -> f32 accumulate (legal on plain sm_103 target)
__device__ __forceinline__ void mma16816(float* d, const uint32_t* a,
                                         uint32_t b0, uint32_t b1) {
    asm volatile(
        "mma.sync.aligned.m16n8k16.row.col.f32.bf16.bf16.f32 "
        "{%0,%1,%2,%3}, {%4,%5,%6,%7}, {%8,%9}, {%0,%1,%2,%3};"
        : "+f"(d[0]), "+f"(d[1]), "+f"(d[2]), "+f"(d[3])
        : "r"(a[0]), "r"(a[1]), "r"(a[2]), "r"(a[3]), "r"(b0), "r"(b1));
}

// ---------------------------------------------------------------------------
// Weight prep: split all weights into bf16 hi/lo planes
// ---------------------------------------------------------------------------
__global__ void k_wprep(const float* __restrict__ fc0,
                        const float* __restrict__ w1,
                        const float* __restrict__ ws,
                        const float* __restrict__ fcc) {
    int t = blockIdx.x * blockDim.x + threadIdx.x;
    if (t >= WTOTAL) return;
    float v;
    if (t < 163840) {
        v = fc0[t];                               // (NBLK,128,256) contiguous
    } else if (t < 409600) {
        int u = t - 163840;
        int k = u / 49152, r = u % 49152;
        int n = r / 384, c = r % 384;
        if (c < 128) v = w1[((size_t)k * HID + n) * 128 + c];
        else         v = ws[((size_t)k * HID + n) * 256 + (c - 128)];
    } else {
        v = fcc[t - 409600];
    }
    __nv_bfloat16 hi = __float2bfloat16(v);
    float lo = v - __bfloat162float(hi);
    g_wh[t] = hi;
    g_wl[t] = __float2bfloat16(lo);
}

// ---------------------------------------------------------------------------
// fc_pos + bin index
// ---------------------------------------------------------------------------
__global__ void k_pos(const float* __restrict__ pts,
                      const float* __restrict__ w,
                      const float* __restrict__ b) {
    int m = blockIdx.x;
    int j = threadIdx.x;
    float p0 = pts[(size_t)m * 3 + 0];
    float p1 = pts[(size_t)m * 3 + 1];
    float p2 = pts[(size_t)m * 3 + 2];
    float v = b[j] + p0 * w[j * 3 + 0] + p1 * w[j * 3 + 1] + p2 * w[j * 3 + 2];
    g_XH[(size_t)m * LDXH + 128 + j] = v;
    if (j == 0) {
        int gx = (int)(p0 * (float)RESO);
        int gy = (int)(p1 * (float)RESO);
        gx = min(max(gx, 0), RESO - 1);
        gy = min(max(gy, 0), RESO - 1);
        g_idx[m] = gx + RESO * gy;
    }
}

// ---------------------------------------------------------------------------
// mma.sync GEMM: C[M x 128] = act(A[M x K]) @ W^T + bias
// CTA: 128x128 tile, 256 thr (8 warps, 4x2), BK=32, bf16 hi/lo (3 MMAs).
// A from g_XH (col a_col0, relu on global k < relu_limit), W from bf16
// hi/lo planes at woff. Output written to g_XH col c_col0.
// smem rows padded to 40 elems -> conflict-free frag loads.
// ---------------------------------------------------------------------------
#define BKP 40
__global__ void __launch_bounds__(256, 2) k_gemm_mma(
    int a_col0, size_t woff, int K, int relu_limit,
    const float* __restrict__ bias, int c_col0)
{
    __shared__ __align__(16) __nv_bfloat16 sAh[128 * BKP];
    __shared__ __align__(16) __nv_bfloat16 sAl[128 * BKP];
    __shared__ __align__(16) __nv_bfloat16 sWh[128 * BKP];
    __shared__ __align__(16) __nv_bfloat16 sWl[128 * BKP];
    __shared__ float bias_s[128];

    int tid = threadIdx.x;
    int wid = tid >> 5;
    int lid = tid & 31;
    int m0  = blockIdx.x * 128;
    int warp_m = wid & 3;          // 4 warps over M (32 rows each)
    int warp_n = wid >> 2;         // 2 warps over N (64 cols each)
    int g  = lid >> 2;             // groupID 0..7
    int tg = lid & 3;              // thread-in-group

    if (tid < 128) bias_s[tid] = bias[tid];

    float acc[2][8][4];
    #pragma unroll
    for (int mt = 0; mt < 2; mt++)
        #pragma unroll
        for (int nt = 0; nt < 8; nt++)
            #pragma unroll
            for (int r = 0; r < 4; r++) acc[mt][nt][r] = 0.f;

    const float* Abase = g_XH + (size_t)m0 * LDXH + a_col0;
    const uint32_t* A32h = (const uint32_t*)sAh;
    const uint32_t* A32l = (const uint32_t*)sAl;
    const uint32_t* W32h = (const uint32_t*)sWh;
    const uint32_t* W32l = (const uint32_t*)sWl;

    const int nchunks = K >> 5;
    for (int c = 0; c < nchunks; c++) {
        int k0 = c << 5;
        bool dorelu = (k0 < relu_limit);   // relu_limit multiple of 32 -> uniform

        // A chunk: 128 rows x 32 f32 -> relu -> hi/lo bf16 pairs
        #pragma unroll
        for (int i = 0; i < 4; i++) {
            int f = tid + (i << 8);           // 0..1023
            int row = f >> 3;
            int q   = f & 7;                  // float4 index within 32 cols
            float4 v = *(const float4*)(Abase + (size_t)row * LDXH + k0 + (q << 2));
            if (dorelu) {
                v.x = fmaxf(v.x, 0.f); v.y = fmaxf(v.y, 0.f);
                v.z = fmaxf(v.z, 0.f); v.w = fmaxf(v.w, 0.f);
            }
            uint32_t hp0, lp0, hp1, lp1;
            split2(v.x, v.y, hp0, lp0);
            split2(v.z, v.w, hp1, lp1);
            int off = row * BKP + (q << 2);   // element index (even)
            *(uint2*)(sAh + off) = make_uint2(hp0, hp1);
            *(uint2*)(sAl + off) = make_uint2(lp0, lp1);
        }
        // W chunk: 128 rows x 32 bf16 per plane (pre-split)
        #pragma unroll
        for (int i = 0; i < 2; i++) {
            int f = tid + (i << 8);           // 0..511
            int row = f >> 2;
            int u   = f & 3;                  // uint4 (8 bf16) index
            size_t so = woff + (size_t)row * K + k0 + (u << 3);
            uint4 wh = *(const uint4*)(g_wh + so);
            uint4 wl = *(const uint4*)(g_wl + so);
            int off = row * BKP + (u << 3);
            *(uint4*)(sWh + off) = wh;
            *(uint4*)(sWl + off) = wl;
        }
        __syncthreads();

        // Compute: 2 k-steps of 16
        #pragma unroll
        for (int ks = 0; ks < 2; ks++) {
            int kb = (ks << 3) + tg;          // b32 offset within row: ks*16/2 + tg
            uint32_t ah[2][4], al[2][4];
            #pragma unroll
            for (int mt = 0; mt < 2; mt++) {
                int r0 = (warp_m << 5) + (mt << 4) + g;
                int b0 = r0 * (BKP / 2) + kb;
                int b1 = b0 + 8 * (BKP / 2);
                ah[mt][0] = A32h[b0];     ah[mt][1] = A32h[b1];
                ah[mt][2] = A32h[b0 + 4]; ah[mt][3] = A32h[b1 + 4];
                al[mt][0] = A32l[b0];     al[mt][1] = A32l[b1];
                al[mt][2] = A32l[b0 + 4]; al[mt][3] = A32l[b1 + 4];
            }
            #pragma unroll
            for (int nt = 0; nt < 8; nt++) {
                int n  = (warp_n << 6) + (nt << 3) + g;
                int bb = n * (BKP / 2) + kb;
                uint32_t bh0 = W32h[bb], bh1 = W32h[bb + 4];
                uint32_t bl0 = W32l[bb], bl1 = W32l[bb + 4];
                #pragma unroll
                for (int mt = 0; mt < 2; mt++) {
                    mma16816(acc[mt][nt], ah[mt], bh0, bh1);
                    mma16816(acc[mt][nt], ah[mt], bl0, bl1);
                    mma16816(acc[mt][nt], al[mt], bh0, bh1);
                }
            }
        }
        __syncthreads();
    }

    // Epilogue: d0,d1 -> row g, cols tg*2,tg*2+1 ; d2,d3 -> row g+8
    #pragma unroll
    for (int mt = 0; mt < 2; mt++) {
        int row0 = m0 + (warp_m << 5) + (mt << 4) + g;
        #pragma unroll
        for (int nt = 0; nt < 8; nt++) {
            int colL = (warp_n << 6) + (nt << 3) + (tg << 1);
            float b0 = bias_s[colL], b1 = bias_s[colL + 1];
            float2 v0 = make_float2(acc[mt][nt][0] + b0, acc[mt][nt][1] + b1);
            float2 v1 = make_float2(acc[mt][nt][2] + b0, acc[mt][nt][3] + b1);
            *(float2*)(g_XH + (size_t)row0 * LDXH + c_col0 + colL) = v0;
            *(float2*)(g_XH + (size_t)(row0 + 8) * LDXH + c_col0 + colL) = v1;
        }
    }
}

// ---------------------------------------------------------------------------
// Pool / scatter kernels
// ---------------------------------------------------------------------------
__global__ void k_zero() {
    size_t t = (size_t)blockIdx.x * blockDim.x + threadIdx.x;
    const size_t nb = (size_t)BB * R2 * HID;
    if (t < nb) g_bins[t] = 0u;
    if (t < (size_t)BB * R2) g_cnt[t] = 0.f;
}

__global__ void k_smax() {
    int t = blockIdx.x * blockDim.x + threadIdx.x;
    int m = t >> 7, f = t & 127;
    int b = m >> 14;
    float v = g_XH[(size_t)m * LDXH + 128 + f];
    unsigned* dst = &g_bins[((size_t)(b << 14) + g_idx[m]) * HID + f];
    atomicMax(dst, f_enc(v));
}

__global__ void k_gather() {
    int t = blockIdx.x * blockDim.x + threadIdx.x;
    int m = t >> 7, f = t & 127;
    int b = m >> 14;
    unsigned u = g_bins[((size_t)(b << 14) + g_idx[m]) * HID + f];
    g_XH[(size_t)m * LDXH + 256 + f] = f_dec(u);
}

__global__ void k_ssum() {
    int t = blockIdx.x * blockDim.x + threadIdx.x;
    int m = t >> 7, f = t & 127;
    int b = m >> 14;
    float v = g_XH[(size_t)m * LDXH + f];
    float* sums = (float*)g_bins;
    atomicAdd(&sums[((size_t)(b << 14) + g_idx[m]) * HID + f], v);
    if (f == 0) atomicAdd(&g_cnt[(b << 14) + g_idx[m]], 1.0f);
}

__global__ void k_final(float* __restrict__ out) {
    __shared__ float s[32][33];
    __shared__ float sc[32];
    int b    = blockIdx.z;
    int bin0 = blockIdx.x * 32;
    int c0   = blockIdx.y * 32;
    const float* sums = (const float*)g_bins;

    #pragma unroll
    for (int i = 0; i < 4; i++) {
        int binl = threadIdx.y + i * 8;
        s[binl][threadIdx.x] =
            sums[((size_t)(b * R2 + bin0 + binl)) * HID + c0 + threadIdx.x];
    }
    if (threadIdx.y == 0)
        sc[threadIdx.x] = fmaxf(g_cnt[b * R2 + bin0 + threadIdx.x], 1.0f);
    __syncthreads();

    #pragma unroll
    for (int i = 0; i < 4; i++) {
        int c = c0 + threadIdx.y + i * 8;
        out[((size_t)(b * HID + c)) * R2 + bin0 + threadIdx.x] =
            s[threadIdx.x][threadIdx.y + i * 8] / sc[threadIdx.x];
    }
}

// ---------------------------------------------------------------------------
// Launch
// ---------------------------------------------------------------------------
extern "C" void kernel_launch(void* const* d_in, const int* in_sizes, int n_in,
                              void* d_out, int out_size) {
    const float* points    = (const float*)d_in[0];
    const float* fc_pos_w  = (const float*)d_in[1];
    const float* fc_pos_b  = (const float*)d_in[2];
    const float* blk_fc0_w = (const float*)d_in[3];
    const float* blk_fc0_b = (const float*)d_in[4];
    const float* blk_fc1_w = (const float*)d_in[5];
    const float* blk_fc1_b = (const float*)d_in[6];
    const float* blk_sc_w  = (const float*)d_in[7];
    const float* fc_c_w    = (const float*)d_in[8];
    const float* fc_c_b    = (const float*)d_in[9];
    float* out = (float*)d_out;

    const int GEMM_BLOCKS = MM / 128;          // 512
    const int PF_BLOCKS   = (MM * HID) / 256;  // 32768

    // Weight hi/lo split prep
    k_wprep<<<(WTOTAL + 255) / 256, 256>>>(blk_fc0_w, blk_fc1_w, blk_sc_w, fc_c_w);

    // fc_pos -> XH[:,128:384], bin indices
    k_pos<<<MM, 256>>>(points, fc_pos_w, fc_pos_b);

    // Block 0
    k_gemm_mma<<<GEMM_BLOCKS, 256>>>(128, WOFF_FC0(0), 256, 256, blk_fc0_b, 0);
    k_gemm_mma<<<GEMM_BLOCKS, 256>>>(0, WOFF_WCAT(0), 384, 128, blk_fc1_b, 128);

    // Blocks 1..4: pool(max) -> concat -> resblock
    for (int k = 1; k < NBLK; k++) {
        k_zero<<<32768, 256>>>();
        k_smax<<<PF_BLOCKS, 256>>>();
        k_gather<<<PF_BLOCKS, 256>>>();
        k_gemm_mma<<<GEMM_BLOCKS, 256>>>(128, WOFF_FC0(k), 256, 256,
                                         blk_fc0_b + k * HID, 0);
        k_gemm_mma<<<GEMM_BLOCKS, 256>>>(0, WOFF_WCAT(k), 384, 128,
                                         blk_fc1_b + k * HID, 128);
    }

    // fc_c
    k_gemm_mma<<<GEMM_BLOCKS, 256>>>(128, WOFF_FCC, 128, 128, fc_c_b, 0);

    // scatter_mean + transposed plane write
    k_zero<<<32768, 256>>>();
    k_ssum<<<PF_BLOCKS, 256>>>();
    dim3 fgrid(R2 / 32, HID / 32, BB);
    dim3 fblk(32, 8);
    k_final<<<fgrid, fblk>>>(out);
}